// round 3
// baseline (speedup 1.0000x reference)
#include <cuda_runtime.h>
#include <cuda_bf16.h>
#include <math.h>

// Problem constants (fixed by the dataset)
#define BATCH 2
#define SEQ   1024
#define DMODEL 1024
#define NHEAD 16
#define DH    64
#define MAXREL 16
#define NREL  33           // 2*MAXREL+1
#define MROWS (BATCH*SEQ)  // 2048

// Scratch (allocation-free rule: __device__ globals)
__device__ float g_q[MROWS * DMODEL];
__device__ float g_k[MROWS * DMODEL];
__device__ float g_v[MROWS * DMODEL];
__device__ float g_x[MROWS * DMODEL];

// ---------------------------------------------------------------------------
// SGEMM core: C[M,N] = A[M,K] @ W[K,N] + bias[N]
// 128x128 tile, BK=8, 256 threads, 8x8 per thread, double-buffered smem.
// ---------------------------------------------------------------------------
__device__ __forceinline__ void sgemm_body(
    const float* __restrict__ A, const float* __restrict__ W,
    const float* __restrict__ bias, float* __restrict__ C,
    int N, int Kd, int bx, int by)
{
    const int t = threadIdx.x;

    __shared__ float As[2][8][128];    // transposed A tile: [k][m]
    __shared__ float Bs[2][8][128];    // [k][n]

    const int tx = t & 15;          // 0..15
    const int ty = t >> 4;          // 0..15

    float acc[8][8];
#pragma unroll
    for (int i = 0; i < 8; ++i)
#pragma unroll
        for (int j = 0; j < 8; ++j) acc[i][j] = 0.f;

    const int arow = t >> 1;        // 0..127
    const int acol = (t & 1) * 4;   // 0 or 4
    const int brow = t >> 5;        // 0..7
    const int bcol = (t & 31) * 4;  // 0..124

    const float* Aptr = A + (size_t)(by * 128 + arow) * Kd + acol;
    const float* Wptr = W + (size_t)brow * N + bx * 128 + bcol;

    // Prologue: stage k-slice 0 into buffer 0
    {
        float4 av = *(const float4*)(Aptr);
        As[0][acol + 0][arow] = av.x;
        As[0][acol + 1][arow] = av.y;
        As[0][acol + 2][arow] = av.z;
        As[0][acol + 3][arow] = av.w;
        *(float4*)&Bs[0][brow][bcol] = *(const float4*)(Wptr);
    }
    __syncthreads();

    for (int k0 = 0; k0 < Kd; k0 += 8) {
        const int buf = (k0 >> 3) & 1;
        const bool more = (k0 + 8) < Kd;

        // Prefetch next slice into registers (overlaps with compute below)
        float4 av, bv;
        if (more) {
            av = *(const float4*)(Aptr + k0 + 8);
            bv = *(const float4*)(Wptr + (size_t)(k0 + 8) * N);
        }

#pragma unroll
        for (int k = 0; k < 8; ++k) {
            float4 a0 = *(const float4*)&As[buf][k][ty * 4];
            float4 a1 = *(const float4*)&As[buf][k][64 + ty * 4];
            float4 b0 = *(const float4*)&Bs[buf][k][tx * 4];
            float4 b1 = *(const float4*)&Bs[buf][k][64 + tx * 4];
            float ra[8] = {a0.x, a0.y, a0.z, a0.w, a1.x, a1.y, a1.z, a1.w};
            float rb[8] = {b0.x, b0.y, b0.z, b0.w, b1.x, b1.y, b1.z, b1.w};
#pragma unroll
            for (int i = 0; i < 8; ++i)
#pragma unroll
                for (int j = 0; j < 8; ++j) acc[i][j] += ra[i] * rb[j];
        }

        if (more) {
            const int nb = buf ^ 1;
            As[nb][acol + 0][arow] = av.x;
            As[nb][acol + 1][arow] = av.y;
            As[nb][acol + 2][arow] = av.z;
            As[nb][acol + 3][arow] = av.w;
            *(float4*)&Bs[nb][brow][bcol] = bv;
        }
        __syncthreads();
    }

    // Epilogue
#pragma unroll
    for (int i = 0; i < 8; ++i) {
        int m = by * 128 + ((i < 4) ? (ty * 4 + i) : (64 + ty * 4 + (i - 4)));
#pragma unroll
        for (int jj = 0; jj < 2; ++jj) {
            int ncol = bx * 128 + ((jj == 0) ? (tx * 4) : (64 + tx * 4));
            float4 o;
            o.x = acc[i][jj * 4 + 0] + bias[ncol + 0];
            o.y = acc[i][jj * 4 + 1] + bias[ncol + 1];
            o.z = acc[i][jj * 4 + 2] + bias[ncol + 2];
            o.w = acc[i][jj * 4 + 3] + bias[ncol + 3];
            *(float4*)&C[(size_t)m * N + ncol] = o;
        }
    }
}

// Single GEMM (output projection)
__global__ __launch_bounds__(256) void sgemm_bias(
    const float* __restrict__ A, const float* __restrict__ W,
    const float* __restrict__ bias, float* __restrict__ C,
    int N, int Kd)
{
    sgemm_body(A, W, bias, C, N, Kd, blockIdx.x, blockIdx.y);
}

// Fused Q/K/V projections: blockIdx.z selects which GEMM.
// 3*128 = 384 CTAs fills the 148-SM chip instead of 3 x 128-CTA partial waves.
__global__ __launch_bounds__(256) void sgemm_bias_qkv(
    const float* __restrict__ Aq, const float* __restrict__ Ak, const float* __restrict__ Av,
    const float* __restrict__ Wq, const float* __restrict__ Wk, const float* __restrict__ Wv,
    const float* __restrict__ bq, const float* __restrict__ bk, const float* __restrict__ bv,
    float* __restrict__ Cq, float* __restrict__ Ck, float* __restrict__ Cv,
    int N, int Kd)
{
    const int z = blockIdx.z;
    const float* A = (z == 0) ? Aq : (z == 1) ? Ak : Av;
    const float* W = (z == 0) ? Wq : (z == 1) ? Wk : Wv;
    const float* b = (z == 0) ? bq : (z == 1) ? bk : bv;
    float*       C = (z == 0) ? Cq : (z == 1) ? Ck : Cv;
    sgemm_body(A, W, b, C, N, Kd, blockIdx.x, blockIdx.y);
}

// ---------------------------------------------------------------------------
// Fused relative-position attention, flash-style online softmax.
// Block = (q-tile of 32 rows, head h, batch b). 256 threads.
//   attn logits  = (q.k + q.rel_k[idx(q,k)]) / sqrt(dh)   (q pre-scaled)
//   output       = softmax @ v + bucket_sums @ rel_v
// ---------------------------------------------------------------------------
#define QT 32
#define KT 32

__global__ __launch_bounds__(256) void attn_kernel(
    const float* __restrict__ Q, const float* __restrict__ Kp,
    const float* __restrict__ Vp, const float* __restrict__ relk,
    const float* __restrict__ relv, float* __restrict__ X)
{
    const int t  = threadIdx.x;
    const int qt = blockIdx.x;   // 0..SEQ/QT-1
    const int h  = blockIdx.y;   // 0..15
    const int b  = blockIdx.z;   // 0..1
    const int q0 = qt * QT;

    __shared__ float sq[QT][DH + 1];     // q tile, pre-scaled by 1/sqrt(dh)
    __shared__ float kt[KT][DH + 1];
    __shared__ float vt[KT][DH + 1];
    __shared__ float st[QT][KT + 1];     // score/probability tile
    __shared__ float qrel[QT][NREL];     // q . rel_k[r]
    __shared__ float srel[QT][NREL];     // running bucket probability sums
    __shared__ float rowm[QT], rowl[QT];

    const float inv_scale = 0.125f;      // 1/sqrt(64)

    const float* qbase = Q  + ((size_t)b * SEQ) * DMODEL + h * DH;
    const float* kbase = Kp + ((size_t)b * SEQ) * DMODEL + h * DH;
    const float* vbase = Vp + ((size_t)b * SEQ) * DMODEL + h * DH;

    // Load q tile (coalesced, 64-float runs), pre-scale
#pragma unroll
    for (int i = 0; i < (QT * DH) / 256; ++i) {
        int idx = i * 256 + t;
        int r = idx >> 6, c = idx & 63;
        sq[r][c] = qbase[(size_t)(q0 + r) * DMODEL + c] * inv_scale;
    }
    if (t < QT) { rowm[t] = -INFINITY; rowl[t] = 0.f; }
    for (int i = t; i < QT * NREL; i += 256) srel[i / NREL][i % NREL] = 0.f;
    __syncthreads();

    // qrel[r][rr] = sq[r] . rel_k[rr]   (1056 small dots)
    for (int i = t; i < QT * NREL; i += 256) {
        int r = i / NREL, rr = i % NREL;
        const float* rp = relk + rr * DH;
        float s = 0.f;
#pragma unroll
        for (int d = 0; d < DH; ++d) s += sq[r][d] * rp[d];
        qrel[r][rr] = s;
    }
    __syncthreads();

    const int qr = t >> 3;   // row owned for stats/AV: 0..31
    const int g  = t & 7;    // 8 lanes per row
    float acc[8];
#pragma unroll
    for (int j = 0; j < 8; ++j) acc[j] = 0.f;

    for (int kb = 0; kb < SEQ / KT; ++kb) {
        const int k0 = kb * KT;

        // Stage K,V tiles (coalesced)
#pragma unroll
        for (int i = 0; i < (KT * DH) / 256; ++i) {
            int idx = i * 256 + t;
            int r = idx >> 6, c = idx & 63;
            kt[r][c] = kbase[(size_t)(k0 + r) * DMODEL + c];
            vt[r][c] = vbase[(size_t)(k0 + r) * DMODEL + c];
        }
        __syncthreads();

        // Scores: thread computes 4 rows for its kc column (kt reused 4x)
        {
            const int kc = t & 31;
            const int qb0 = t >> 5;        // 0..7
            float s0 = 0.f, s1 = 0.f, s2 = 0.f, s3 = 0.f;
#pragma unroll
            for (int d = 0; d < DH; ++d) {
                float kv = kt[kc][d];
                s0 += sq[qb0][d]      * kv;
                s1 += sq[qb0 + 8][d]  * kv;
                s2 += sq[qb0 + 16][d] * kv;
                s3 += sq[qb0 + 24][d] * kv;
            }
            const int d0 = (k0 + kc) - (q0 + qb0);
            int r0 = min(max(d0,      -MAXREL), MAXREL) + MAXREL;
            int r1 = min(max(d0 - 8,  -MAXREL), MAXREL) + MAXREL;
            int r2 = min(max(d0 - 16, -MAXREL), MAXREL) + MAXREL;
            int r3 = min(max(d0 - 24, -MAXREL), MAXREL) + MAXREL;
            st[qb0][kc]      = s0 + qrel[qb0][r0];
            st[qb0 + 8][kc]  = s1 + qrel[qb0 + 8][r1];
            st[qb0 + 16][kc] = s2 + qrel[qb0 + 16][r2];
            st[qb0 + 24][kc] = s3 + qrel[qb0 + 24][r3];
        }
        __syncthreads();

        // Online softmax stats per row (8 lanes/row, warp-local)
        {
            float lm = -INFINITY;
#pragma unroll
            for (int i = 0; i < 4; ++i) lm = fmaxf(lm, st[qr][g * 4 + i]);
#pragma unroll
            for (int o = 4; o >= 1; o >>= 1)
                lm = fmaxf(lm, __shfl_xor_sync(0xffffffffu, lm, o));

            float mold = rowm[qr];
            float mnew = fmaxf(mold, lm);
            float factor = __expf(mold - mnew);

            float lsum = 0.f;
#pragma unroll
            for (int i = 0; i < 4; ++i) {
                float p = __expf(st[qr][g * 4 + i] - mnew);
                st[qr][g * 4 + i] = p;
                lsum += p;
            }
#pragma unroll
            for (int o = 4; o >= 1; o >>= 1)
                lsum += __shfl_xor_sync(0xffffffffu, lsum, o);

            // rescale running state
#pragma unroll
            for (int j = 0; j < 8; ++j) acc[j] *= factor;
            for (int r = g; r < NREL; r += 8) srel[qr][r] *= factor;
            __syncwarp();

            if (g == 0) {
                rowl[qr] = rowl[qr] * factor + lsum;
                rowm[qr] = mnew;
                int dd = k0 - (q0 + qr);
                for (int kc = 0; kc < KT; ++kc) {
                    int rr = min(max(dd + kc, -MAXREL), MAXREL) + MAXREL;
                    srel[qr][rr] += st[qr][kc];
                }
            }
            __syncwarp();

            // AV accumulate: this thread owns d = g*8 .. g*8+7 of its row
            const int dbase = g * 8;
#pragma unroll 4
            for (int kc = 0; kc < KT; ++kc) {
                float p = st[qr][kc];
#pragma unroll
                for (int j = 0; j < 8; ++j) acc[j] += p * vt[kc][dbase + j];
            }
        }
        __syncthreads();
    }

    // Finalize: add bucket_sums @ rel_v, normalize, write
    {
        const int dbase = g * 8;
        float invl = 1.0f / rowl[qr];
        float outv[8];
#pragma unroll
        for (int j = 0; j < 8; ++j) outv[j] = acc[j];
        for (int r = 0; r < NREL; ++r) {
            float srv = srel[qr][r];
            const float* rp = relv + r * DH + dbase;
#pragma unroll
            for (int j = 0; j < 8; ++j) outv[j] += srv * rp[j];
        }
        float* xo = X + ((size_t)b * SEQ + q0 + qr) * DMODEL + h * DH + dbase;
#pragma unroll
        for (int j = 0; j < 8; ++j) xo[j] = outv[j] * invl;
    }
}

// ---------------------------------------------------------------------------
extern "C" void kernel_launch(void* const* d_in, const int* in_sizes, int n_in,
                              void* d_out, int out_size)
{
    const float* query = (const float*)d_in[0];
    const float* key   = (const float*)d_in[1];
    const float* value = (const float*)d_in[2];
    const float* Wq = (const float*)d_in[3];  const float* bq = (const float*)d_in[4];
    const float* Wk = (const float*)d_in[5];  const float* bk = (const float*)d_in[6];
    const float* Wv = (const float*)d_in[7];  const float* bv = (const float*)d_in[8];
    const float* Wo = (const float*)d_in[9];  const float* bo = (const float*)d_in[10];
    const float* relk = (const float*)d_in[11];
    const float* relv = (const float*)d_in[12];
    float* out = (float*)d_out;

    float *gq, *gk, *gv, *gx;
    cudaGetSymbolAddress((void**)&gq, g_q);
    cudaGetSymbolAddress((void**)&gk, g_k);
    cudaGetSymbolAddress((void**)&gv, g_v);
    cudaGetSymbolAddress((void**)&gx, g_x);

    // Fused Q/K/V projections: 384 CTAs in one wave set
    dim3 qkvgrid(DMODEL / 128, MROWS / 128, 3);   // (8, 16, 3)
    sgemm_bias_qkv<<<qkvgrid, 256>>>(query, key, value,
                                     Wq, Wk, Wv, bq, bk, bv,
                                     gq, gk, gv, DMODEL, DMODEL);

    dim3 agrid(SEQ / QT, NHEAD, BATCH);           // (32, 16, 2)
    attn_kernel<<<agrid, 256>>>(gq, gk, gv, relk, relv, gx);

    dim3 ggrid(DMODEL / 128, MROWS / 128);        // (8, 16)
    sgemm_bias<<<ggrid, 256>>>(gx, Wo, bo, out, DMODEL, DMODEL);
}

// round 4
// speedup vs baseline: 1.5952x; 1.5952x over previous
#include <cuda_runtime.h>
#include <cuda_bf16.h>
#include <math.h>

// Problem constants (fixed by the dataset)
#define BATCH 2
#define SEQ   1024
#define DMODEL 1024
#define NHEAD 16
#define DH    64
#define MAXREL 16
#define NREL  33           // 2*MAXREL+1
#define MROWS (BATCH*SEQ)  // 2048

// Scratch (allocation-free rule: __device__ globals)
__device__ float g_q[MROWS * DMODEL];
__device__ float g_k[MROWS * DMODEL];
__device__ float g_v[MROWS * DMODEL];
__device__ float g_x[MROWS * DMODEL];

// ---------------------------------------------------------------------------
// SGEMM core: C[M,N] = A[M,K] @ W[K,N] + bias[N]
// 128x128 tile, BK=8, 256 threads, 8x8 per thread, double-buffered smem.
// ---------------------------------------------------------------------------
__device__ __forceinline__ void sgemm_body(
    const float* __restrict__ A, const float* __restrict__ W,
    const float* __restrict__ bias, float* __restrict__ C,
    int N, int Kd, int bx, int by)
{
    const int t = threadIdx.x;

    __shared__ float As[2][8][128];    // transposed A tile: [k][m]
    __shared__ float Bs[2][8][128];    // [k][n]

    const int tx = t & 15;          // 0..15
    const int ty = t >> 4;          // 0..15

    float acc[8][8];
#pragma unroll
    for (int i = 0; i < 8; ++i)
#pragma unroll
        for (int j = 0; j < 8; ++j) acc[i][j] = 0.f;

    const int arow = t >> 1;        // 0..127
    const int acol = (t & 1) * 4;   // 0 or 4
    const int brow = t >> 5;        // 0..7
    const int bcol = (t & 31) * 4;  // 0..124

    const float* Aptr = A + (size_t)(by * 128 + arow) * Kd + acol;
    const float* Wptr = W + (size_t)brow * N + bx * 128 + bcol;

    {
        float4 av = *(const float4*)(Aptr);
        As[0][acol + 0][arow] = av.x;
        As[0][acol + 1][arow] = av.y;
        As[0][acol + 2][arow] = av.z;
        As[0][acol + 3][arow] = av.w;
        *(float4*)&Bs[0][brow][bcol] = *(const float4*)(Wptr);
    }
    __syncthreads();

    for (int k0 = 0; k0 < Kd; k0 += 8) {
        const int buf = (k0 >> 3) & 1;
        const bool more = (k0 + 8) < Kd;

        float4 av, bv;
        if (more) {
            av = *(const float4*)(Aptr + k0 + 8);
            bv = *(const float4*)(Wptr + (size_t)(k0 + 8) * N);
        }

#pragma unroll
        for (int k = 0; k < 8; ++k) {
            float4 a0 = *(const float4*)&As[buf][k][ty * 4];
            float4 a1 = *(const float4*)&As[buf][k][64 + ty * 4];
            float4 b0 = *(const float4*)&Bs[buf][k][tx * 4];
            float4 b1 = *(const float4*)&Bs[buf][k][64 + tx * 4];
            float ra[8] = {a0.x, a0.y, a0.z, a0.w, a1.x, a1.y, a1.z, a1.w};
            float rb[8] = {b0.x, b0.y, b0.z, b0.w, b1.x, b1.y, b1.z, b1.w};
#pragma unroll
            for (int i = 0; i < 8; ++i)
#pragma unroll
                for (int j = 0; j < 8; ++j) acc[i][j] += ra[i] * rb[j];
        }

        if (more) {
            const int nb = buf ^ 1;
            As[nb][acol + 0][arow] = av.x;
            As[nb][acol + 1][arow] = av.y;
            As[nb][acol + 2][arow] = av.z;
            As[nb][acol + 3][arow] = av.w;
            *(float4*)&Bs[nb][brow][bcol] = bv;
        }
        __syncthreads();
    }

#pragma unroll
    for (int i = 0; i < 8; ++i) {
        int m = by * 128 + ((i < 4) ? (ty * 4 + i) : (64 + ty * 4 + (i - 4)));
#pragma unroll
        for (int jj = 0; jj < 2; ++jj) {
            int ncol = bx * 128 + ((jj == 0) ? (tx * 4) : (64 + tx * 4));
            float4 o;
            o.x = acc[i][jj * 4 + 0] + bias[ncol + 0];
            o.y = acc[i][jj * 4 + 1] + bias[ncol + 1];
            o.z = acc[i][jj * 4 + 2] + bias[ncol + 2];
            o.w = acc[i][jj * 4 + 3] + bias[ncol + 3];
            *(float4*)&C[(size_t)m * N + ncol] = o;
        }
    }
}

__global__ __launch_bounds__(256) void sgemm_bias(
    const float* __restrict__ A, const float* __restrict__ W,
    const float* __restrict__ bias, float* __restrict__ C,
    int N, int Kd)
{
    sgemm_body(A, W, bias, C, N, Kd, blockIdx.x, blockIdx.y);
}

__global__ __launch_bounds__(256) void sgemm_bias_qkv(
    const float* __restrict__ Aq, const float* __restrict__ Ak, const float* __restrict__ Av,
    const float* __restrict__ Wq, const float* __restrict__ Wk, const float* __restrict__ Wv,
    const float* __restrict__ bq, const float* __restrict__ bk, const float* __restrict__ bv,
    float* __restrict__ Cq, float* __restrict__ Ck, float* __restrict__ Cv,
    int N, int Kd)
{
    const int z = blockIdx.z;
    const float* A = (z == 0) ? Aq : (z == 1) ? Ak : Av;
    const float* W = (z == 0) ? Wq : (z == 1) ? Wk : Wv;
    const float* b = (z == 0) ? bq : (z == 1) ? bk : bv;
    float*       C = (z == 0) ? Cq : (z == 1) ? Ck : Cv;
    sgemm_body(A, W, b, C, N, Kd, blockIdx.x, blockIdx.y);
}

// ---------------------------------------------------------------------------
// Fused relative-position attention v2: register-tiled GEMM phases.
// Block = (64 q-rows, head h, batch b), 256 threads, 4x4 micro-tiles.
// smem layouts: sqT/ktT d-major [d][q|k], stT k-major [k][q], vt natural [k][d].
// ---------------------------------------------------------------------------
#define QT 64
#define KT 64
#define LD 68   // padded leading dim (floats)

// dynamic smem layout (floats):
//   sqT  [64][LD]   ktT [64][LD]   vt [64][LD]   stT [64][LD]
//   qrel [64][33]   srel[64][33]   rowm[64] rowl[64] sfac[64]
#define ATTN_SMEM_FLOATS (4*64*LD + 2*64*NREL + 3*64)

__global__ __launch_bounds__(256, 2) void attn_kernel(
    const float* __restrict__ Q, const float* __restrict__ Kp,
    const float* __restrict__ Vp, const float* __restrict__ relk,
    const float* __restrict__ relv, float* __restrict__ X)
{
    extern __shared__ float sm[];
    float* sqT  = sm;                       // [d][q]
    float* ktT  = sqT + 64 * LD;            // [d][k]
    float* vt   = ktT + 64 * LD;            // [k][d]
    float* stT  = vt  + 64 * LD;            // [k][q]
    float* qrel = stT + 64 * LD;            // [q][33]
    float* srel = qrel + 64 * NREL;         // [q][33]
    float* rowm = srel + 64 * NREL;
    float* rowl = rowm + 64;
    float* sfac = rowl + 64;

    const int t  = threadIdx.x;
    const int q0 = blockIdx.x * QT;
    const int h  = blockIdx.y;
    const int b  = blockIdx.z;

    const float* qbase = Q  + ((size_t)b * SEQ) * DMODEL + h * DH;
    const float* kbase = Kp + ((size_t)b * SEQ) * DMODEL + h * DH;
    const float* vbase = Vp + ((size_t)b * SEQ) * DMODEL + h * DH;

    // ---- Load Q tile transposed (pre-scaled), init state ----
#pragma unroll
    for (int i = 0; i < (QT * DH) / 256; ++i) {
        int idx = i * 256 + t;
        int r = idx >> 6, c = idx & 63;
        sqT[c * LD + r] = qbase[(size_t)(q0 + r) * DMODEL + c] * 0.125f;
    }
    if (t < 64) { rowm[t] = -INFINITY; rowl[t] = 0.f; }
    for (int i = t; i < 64 * NREL; i += 256) srel[i] = 0.f;
    __syncthreads();

    // ---- qrel[r][rr] = sq[r] . rel_k[rr] ----
    for (int i = t; i < QT * NREL; i += 256) {
        int r = i / NREL, rr = i % NREL;
        const float* rp = relk + rr * DH;
        float s = 0.f;
#pragma unroll
        for (int d = 0; d < DH; ++d) s += sqT[d * LD + r] * rp[d];
        qrel[r * NREL + rr] = s;
    }
    __syncthreads();

    const int qg = (t & 15) * 4;   // q micro-tile base (score & AV)
    const int kg = (t >> 4) * 4;   // k micro-tile base (score)
    const int dg = (t >> 4) * 4;   // d micro-tile base (AV)
    const int sq_row = t >> 2;     // softmax: row owned (0..63)
    const int sg     = t & 3;      // softmax: 4 lanes per row

    float o[4][4];
#pragma unroll
    for (int i = 0; i < 4; ++i)
#pragma unroll
        for (int j = 0; j < 4; ++j) o[i][j] = 0.f;

    for (int kb = 0; kb < SEQ / KT; ++kb) {
        const int k0 = kb * KT;

        // ---- Stage K (transposed) and V (natural) ----
#pragma unroll
        for (int i = 0; i < (KT * DH) / 256; ++i) {
            int idx = i * 256 + t;
            int r = idx >> 6, c = idx & 63;
            ktT[c * LD + r] = kbase[(size_t)(k0 + r) * DMODEL + c];
            vt [r * LD + c] = vbase[(size_t)(k0 + r) * DMODEL + c];
        }
        __syncthreads();

        // ---- Score GEMM: st[k][q] = sum_d sqT[d][q]*ktT[d][k] + rel ----
        {
            float acc[4][4];
#pragma unroll
            for (int i = 0; i < 4; ++i)
#pragma unroll
                for (int j = 0; j < 4; ++j) acc[i][j] = 0.f;

#pragma unroll 8
            for (int d = 0; d < DH; ++d) {
                float4 a = *(const float4*)&sqT[d * LD + qg];
                float4 bfr = *(const float4*)&ktT[d * LD + kg];
                float ra[4] = {a.x, a.y, a.z, a.w};
                float rb[4] = {bfr.x, bfr.y, bfr.z, bfr.w};
#pragma unroll
                for (int i = 0; i < 4; ++i)
#pragma unroll
                    for (int j = 0; j < 4; ++j) acc[i][j] += ra[i] * rb[j];
            }
            const int base = k0 + kg - q0 - qg;
#pragma unroll
            for (int i = 0; i < 4; ++i)
#pragma unroll
                for (int j = 0; j < 4; ++j) {
                    int dd = base + j - i;
                    int rr = min(max(dd, -MAXREL), MAXREL) + MAXREL;
                    acc[i][j] += qrel[(qg + i) * NREL + rr];
                }
#pragma unroll
            for (int j = 0; j < 4; ++j) {
                float4 v4 = make_float4(acc[0][j], acc[1][j], acc[2][j], acc[3][j]);
                *(float4*)&stT[(kg + j) * LD + qg] = v4;
            }
        }
        __syncthreads();

        // ---- Online softmax (4 lanes per row) ----
        {
            const int kbase0 = sg * 16;
            float s[16];
            float lm = -INFINITY;
#pragma unroll
            for (int i = 0; i < 16; ++i) {
                s[i] = stT[(kbase0 + i) * LD + sq_row];
                lm = fmaxf(lm, s[i]);
            }
            lm = fmaxf(lm, __shfl_xor_sync(0xffffffffu, lm, 1));
            lm = fmaxf(lm, __shfl_xor_sync(0xffffffffu, lm, 2));

            float mold = rowm[sq_row];
            float mnew = fmaxf(mold, lm);
            float factor = __expf(mold - mnew);

            float lsum = 0.f;
#pragma unroll
            for (int i = 0; i < 16; ++i) {
                s[i] = __expf(s[i] - mnew);
                stT[(kbase0 + i) * LD + sq_row] = s[i];
                lsum += s[i];
            }
            lsum += __shfl_xor_sync(0xffffffffu, lsum, 1);
            lsum += __shfl_xor_sync(0xffffffffu, lsum, 2);

            if (sg == 0) {
                rowl[sq_row] = rowl[sq_row] * factor + lsum;
                rowm[sq_row] = mnew;
                sfac[sq_row] = factor;
            }
            // rescale srel (4 lanes cover 33 buckets)
            for (int rr = sg; rr < NREL; rr += 4)
                srel[sq_row * NREL + rr] *= factor;
            __syncwarp();

            // bucket accumulation: interior rr unique per k; ends reduced
            float c0 = 0.f, c32 = 0.f;
            const int ddb = k0 + kbase0 - (q0 + sq_row);
#pragma unroll
            for (int i = 0; i < 16; ++i) {
                int dd = ddb + i;
                if (dd <= -MAXREL)      c0  += s[i];
                else if (dd >= MAXREL)  c32 += s[i];
                else                    srel[sq_row * NREL + dd + MAXREL] += s[i];
            }
            c0  += __shfl_xor_sync(0xffffffffu, c0, 1);
            c0  += __shfl_xor_sync(0xffffffffu, c0, 2);
            c32 += __shfl_xor_sync(0xffffffffu, c32, 1);
            c32 += __shfl_xor_sync(0xffffffffu, c32, 2);
            if (sg == 0) {
                srel[sq_row * NREL + 0]  += c0;
                srel[sq_row * NREL + 32] += c32;
            }
        }
        __syncthreads();

        // ---- AV GEMM: o[q][d] = o*factor + sum_k p[k][q]*v[k][d] ----
        {
#pragma unroll
            for (int i = 0; i < 4; ++i) {
                float f = sfac[qg + i];
#pragma unroll
                for (int j = 0; j < 4; ++j) o[i][j] *= f;
            }
#pragma unroll 8
            for (int kc = 0; kc < KT; ++kc) {
                float4 a = *(const float4*)&stT[kc * LD + qg];
                float4 bfr = *(const float4*)&vt[kc * LD + dg];
                float ra[4] = {a.x, a.y, a.z, a.w};
                float rb[4] = {bfr.x, bfr.y, bfr.z, bfr.w};
#pragma unroll
                for (int i = 0; i < 4; ++i)
#pragma unroll
                    for (int j = 0; j < 4; ++j) o[i][j] += ra[i] * rb[j];
            }
        }
        __syncthreads();
    }

    // ---- Finalize: add srel @ rel_v, normalize, write ----
    {
#pragma unroll 4
        for (int rr = 0; rr < NREL; ++rr) {
            const float* rp = relv + rr * DH + dg;
            float rv[4] = {rp[0], rp[1], rp[2], rp[3]};
#pragma unroll
            for (int i = 0; i < 4; ++i) {
                float srv = srel[(qg + i) * NREL + rr];
#pragma unroll
                for (int j = 0; j < 4; ++j) o[i][j] += srv * rv[j];
            }
        }
#pragma unroll
        for (int i = 0; i < 4; ++i) {
            float invl = 1.0f / rowl[qg + i];
            float4 v4 = make_float4(o[i][0] * invl, o[i][1] * invl,
                                    o[i][2] * invl, o[i][3] * invl);
            *(float4*)&X[((size_t)b * SEQ + q0 + qg + i) * DMODEL + h * DH + dg] = v4;
        }
    }
}

// ---------------------------------------------------------------------------
extern "C" void kernel_launch(void* const* d_in, const int* in_sizes, int n_in,
                              void* d_out, int out_size)
{
    const float* query = (const float*)d_in[0];
    const float* key   = (const float*)d_in[1];
    const float* value = (const float*)d_in[2];
    const float* Wq = (const float*)d_in[3];  const float* bq = (const float*)d_in[4];
    const float* Wk = (const float*)d_in[5];  const float* bk = (const float*)d_in[6];
    const float* Wv = (const float*)d_in[7];  const float* bv = (const float*)d_in[8];
    const float* Wo = (const float*)d_in[9];  const float* bo = (const float*)d_in[10];
    const float* relk = (const float*)d_in[11];
    const float* relv = (const float*)d_in[12];
    float* out = (float*)d_out;

    float *gq, *gk, *gv, *gx;
    cudaGetSymbolAddress((void**)&gq, g_q);
    cudaGetSymbolAddress((void**)&gk, g_k);
    cudaGetSymbolAddress((void**)&gv, g_v);
    cudaGetSymbolAddress((void**)&gx, g_x);

    const int attn_smem = ATTN_SMEM_FLOATS * sizeof(float);   // ~87 KB
    cudaFuncSetAttribute(attn_kernel,
                         cudaFuncAttributeMaxDynamicSharedMemorySize, attn_smem);

    // Fused Q/K/V projections: 384 CTAs in one wave set
    dim3 qkvgrid(DMODEL / 128, MROWS / 128, 3);   // (8, 16, 3)
    sgemm_bias_qkv<<<qkvgrid, 256>>>(query, key, value,
                                     Wq, Wk, Wv, bq, bk, bv,
                                     gq, gk, gv, DMODEL, DMODEL);

    dim3 agrid(SEQ / QT, NHEAD, BATCH);           // (16, 16, 2)
    attn_kernel<<<agrid, 256, attn_smem>>>(gq, gk, gv, relk, relv, gx);

    dim3 ggrid(DMODEL / 128, MROWS / 128);        // (8, 16)
    sgemm_bias<<<ggrid, 256>>>(gx, Wo, bo, out, DMODEL, DMODEL);
}

// round 5
// speedup vs baseline: 1.9191x; 1.2030x over previous
#include <cuda_runtime.h>
#include <cuda_bf16.h>
#include <math.h>

// Problem constants (fixed by the dataset)
#define BATCH 2
#define SEQ   1024
#define DMODEL 1024
#define NHEAD 16
#define DH    64
#define MAXREL 16
#define NREL  33           // 2*MAXREL+1
#define MROWS (BATCH*SEQ)  // 2048

// Scratch (allocation-free rule: __device__ globals)
__device__ float g_q[MROWS * DMODEL];
__device__ float g_k[MROWS * DMODEL];
__device__ float g_v[MROWS * DMODEL];
__device__ float g_x[MROWS * DMODEL];

// ---------------------------------------------------------------------------
// SGEMM core: C[M,N] = A[M,K] @ W[K,N] + bias[N]
// 128x128 tile, BK=8, 256 threads, 8x8 per thread, double-buffered smem.
// ---------------------------------------------------------------------------
__device__ __forceinline__ void sgemm_body(
    const float* __restrict__ A, const float* __restrict__ W,
    const float* __restrict__ bias, float* __restrict__ C,
    int N, int Kd, int bx, int by)
{
    const int t = threadIdx.x;

    __shared__ float As[2][8][128];    // transposed A tile: [k][m]
    __shared__ float Bs[2][8][128];    // [k][n]

    const int tx = t & 15;          // 0..15
    const int ty = t >> 4;          // 0..15

    float acc[8][8];
#pragma unroll
    for (int i = 0; i < 8; ++i)
#pragma unroll
        for (int j = 0; j < 8; ++j) acc[i][j] = 0.f;

    const int arow = t >> 1;        // 0..127
    const int acol = (t & 1) * 4;   // 0 or 4
    const int brow = t >> 5;        // 0..7
    const int bcol = (t & 31) * 4;  // 0..124

    const float* Aptr = A + (size_t)(by * 128 + arow) * Kd + acol;
    const float* Wptr = W + (size_t)brow * N + bx * 128 + bcol;

    {
        float4 av = *(const float4*)(Aptr);
        As[0][acol + 0][arow] = av.x;
        As[0][acol + 1][arow] = av.y;
        As[0][acol + 2][arow] = av.z;
        As[0][acol + 3][arow] = av.w;
        *(float4*)&Bs[0][brow][bcol] = *(const float4*)(Wptr);
    }
    __syncthreads();

    for (int k0 = 0; k0 < Kd; k0 += 8) {
        const int buf = (k0 >> 3) & 1;
        const bool more = (k0 + 8) < Kd;

        float4 av, bv;
        if (more) {
            av = *(const float4*)(Aptr + k0 + 8);
            bv = *(const float4*)(Wptr + (size_t)(k0 + 8) * N);
        }

#pragma unroll
        for (int k = 0; k < 8; ++k) {
            float4 a0 = *(const float4*)&As[buf][k][ty * 4];
            float4 a1 = *(const float4*)&As[buf][k][64 + ty * 4];
            float4 b0 = *(const float4*)&Bs[buf][k][tx * 4];
            float4 b1 = *(const float4*)&Bs[buf][k][64 + tx * 4];
            float ra[8] = {a0.x, a0.y, a0.z, a0.w, a1.x, a1.y, a1.z, a1.w};
            float rb[8] = {b0.x, b0.y, b0.z, b0.w, b1.x, b1.y, b1.z, b1.w};
#pragma unroll
            for (int i = 0; i < 8; ++i)
#pragma unroll
                for (int j = 0; j < 8; ++j) acc[i][j] += ra[i] * rb[j];
        }

        if (more) {
            const int nb = buf ^ 1;
            As[nb][acol + 0][arow] = av.x;
            As[nb][acol + 1][arow] = av.y;
            As[nb][acol + 2][arow] = av.z;
            As[nb][acol + 3][arow] = av.w;
            *(float4*)&Bs[nb][brow][bcol] = bv;
        }
        __syncthreads();
    }

#pragma unroll
    for (int i = 0; i < 8; ++i) {
        int m = by * 128 + ((i < 4) ? (ty * 4 + i) : (64 + ty * 4 + (i - 4)));
#pragma unroll
        for (int jj = 0; jj < 2; ++jj) {
            int ncol = bx * 128 + ((jj == 0) ? (tx * 4) : (64 + tx * 4));
            float4 o;
            o.x = acc[i][jj * 4 + 0] + bias[ncol + 0];
            o.y = acc[i][jj * 4 + 1] + bias[ncol + 1];
            o.z = acc[i][jj * 4 + 2] + bias[ncol + 2];
            o.w = acc[i][jj * 4 + 3] + bias[ncol + 3];
            *(float4*)&C[(size_t)m * N + ncol] = o;
        }
    }
}

__global__ __launch_bounds__(256) void sgemm_bias(
    const float* __restrict__ A, const float* __restrict__ W,
    const float* __restrict__ bias, float* __restrict__ C,
    int N, int Kd)
{
    sgemm_body(A, W, bias, C, N, Kd, blockIdx.x, blockIdx.y);
}

__global__ __launch_bounds__(256) void sgemm_bias_qkv(
    const float* __restrict__ Aq, const float* __restrict__ Ak, const float* __restrict__ Av,
    const float* __restrict__ Wq, const float* __restrict__ Wk, const float* __restrict__ Wv,
    const float* __restrict__ bq, const float* __restrict__ bk, const float* __restrict__ bv,
    float* __restrict__ Cq, float* __restrict__ Ck, float* __restrict__ Cv,
    int N, int Kd)
{
    const int z = blockIdx.z;
    const float* A = (z == 0) ? Aq : (z == 1) ? Ak : Av;
    const float* W = (z == 0) ? Wq : (z == 1) ? Wk : Wv;
    const float* b = (z == 0) ? bq : (z == 1) ? bk : bv;
    float*       C = (z == 0) ? Cq : (z == 1) ? Ck : Cv;
    sgemm_body(A, W, b, C, N, Kd, blockIdx.x, blockIdx.y);
}

// ---------------------------------------------------------------------------
// Fused relative-position attention v3:
//   128 threads/CTA, QT=KT=64, 8x4 micro-tiles, natural [row][d] layouts,
//   register softmax with 16-lane shfl reductions, clipped-tile fast path.
// ---------------------------------------------------------------------------
#define QT 64
#define KT 64
#define LDS 68   // padded row pitch (floats), multiple of 4

// smem floats: sq[64][LDS] kt[64][LDS] vt[64][LDS] stT[64][LDS]
//              qrel[64][NREL] srel[64][NREL] rowm[64] rowl[64]
#define ATTN_SMEM_FLOATS (4*64*LDS + 2*64*NREL + 2*64)

#define RED16MAX(x) do { \
    x = fmaxf(x, __shfl_xor_sync(0xffffffffu, x, 1)); \
    x = fmaxf(x, __shfl_xor_sync(0xffffffffu, x, 2)); \
    x = fmaxf(x, __shfl_xor_sync(0xffffffffu, x, 4)); \
    x = fmaxf(x, __shfl_xor_sync(0xffffffffu, x, 8)); } while (0)
#define RED16SUM(x) do { \
    x += __shfl_xor_sync(0xffffffffu, x, 1); \
    x += __shfl_xor_sync(0xffffffffu, x, 2); \
    x += __shfl_xor_sync(0xffffffffu, x, 4); \
    x += __shfl_xor_sync(0xffffffffu, x, 8); } while (0)

__global__ __launch_bounds__(128, 2) void attn_kernel(
    const float* __restrict__ Q, const float* __restrict__ Kp,
    const float* __restrict__ Vp, const float* __restrict__ relk,
    const float* __restrict__ relv, float* __restrict__ X)
{
    extern __shared__ float sm[];
    float* sq   = sm;                    // [q][d] pre-scaled
    float* kt   = sq  + 64 * LDS;        // [k][d]
    float* vt   = kt  + 64 * LDS;        // [k][d]
    float* stT  = vt  + 64 * LDS;        // [k][q] probabilities
    float* qrel = stT + 64 * LDS;        // [q][NREL]
    float* srel = qrel + 64 * NREL;      // [q][NREL] running bucket sums
    float* rowm = srel + 64 * NREL;      // [64]
    float* rowl = rowm + 64;             // [64]

    const int t  = threadIdx.x;
    const int q0 = blockIdx.x * QT;
    const int h  = blockIdx.y;
    const int b  = blockIdx.z;

    const float* qbase = Q  + ((size_t)b * SEQ) * DMODEL + h * DH;
    const float* kbase = Kp + ((size_t)b * SEQ) * DMODEL + h * DH;
    const float* vbase = Vp + ((size_t)b * SEQ) * DMODEL + h * DH;

    // ---- Stage Q (natural layout, pre-scaled by 1/8), init state ----
#pragma unroll
    for (int i = 0; i < 8; ++i) {
        int idx = i * 128 + t;
        int r = idx >> 4, c4 = (idx & 15) * 4;
        float4 v = *(const float4*)&qbase[(size_t)(q0 + r) * DMODEL + c4];
        v.x *= 0.125f; v.y *= 0.125f; v.z *= 0.125f; v.w *= 0.125f;
        *(float4*)&sq[r * LDS + c4] = v;
    }
    if (t < 64) { rowm[t] = -INFINITY; rowl[t] = 0.f; }
    for (int i = t; i < 64 * NREL; i += 128) srel[i] = 0.f;
    __syncthreads();

    // ---- qrel[r][rr] = sq[r] . rel_k[rr] ----
    for (int i = t; i < QT * NREL; i += 128) {
        int r = i / NREL, rr = i % NREL;
        const float4* rp = (const float4*)(relk + rr * DH);
        const float4* qp = (const float4*)(sq + r * LDS);
        float s = 0.f;
#pragma unroll
        for (int d4 = 0; d4 < 16; ++d4) {
            float4 a = qp[d4], bb = rp[d4];
            s += a.x * bb.x + a.y * bb.y + a.z * bb.z + a.w * bb.w;
        }
        qrel[r * NREL + rr] = s;
    }
    __syncthreads();

    const int qi = t >> 4;          // 0..7 : q-row group (8 rows)
    const int qg = qi * 8;
    const int l16 = t & 15;         // 16 lanes per group
    const int kg = l16 * 4;         // score: 4 k-cols
    const int di = l16 * 4;         // AV: 4 d-cols

    float o[8][4];
#pragma unroll
    for (int i = 0; i < 8; ++i)
#pragma unroll
        for (int j = 0; j < 4; ++j) o[i][j] = 0.f;

    for (int kb = 0; kb < SEQ / KT; ++kb) {
        const int k0 = kb * KT;

        // ---- Stage K,V (natural, coalesced, conflict-free) ----
#pragma unroll
        for (int i = 0; i < 8; ++i) {
            int idx = i * 128 + t;
            int r = idx >> 4, c4 = (idx & 15) * 4;
            *(float4*)&kt[r * LDS + c4] =
                *(const float4*)&kbase[(size_t)(k0 + r) * DMODEL + c4];
            *(float4*)&vt[r * LDS + c4] =
                *(const float4*)&vbase[(size_t)(k0 + r) * DMODEL + c4];
        }
        __syncthreads();

        // ---- Score: acc[8q][4k] = sum_d sq[q][d]*kt[k][d] ----
        float acc[8][4];
#pragma unroll
        for (int i = 0; i < 8; ++i)
#pragma unroll
            for (int j = 0; j < 4; ++j) acc[i][j] = 0.f;

#pragma unroll 4
        for (int d4 = 0; d4 < DH; d4 += 4) {
            float4 kv[4], qv[8];
#pragma unroll
            for (int j = 0; j < 4; ++j) kv[j] = *(const float4*)&kt[(kg + j) * LDS + d4];
#pragma unroll
            for (int i = 0; i < 8; ++i) qv[i] = *(const float4*)&sq[(qg + i) * LDS + d4];
#pragma unroll
            for (int i = 0; i < 8; ++i)
#pragma unroll
                for (int j = 0; j < 4; ++j) {
                    acc[i][j] += qv[i].x * kv[j].x;
                    acc[i][j] += qv[i].y * kv[j].y;
                    acc[i][j] += qv[i].z * kv[j].z;
                    acc[i][j] += qv[i].w * kv[j].w;
                }
        }

        // ---- Add relative-position bias ----
        const int base = (k0 + kg) - (q0 + qg);
#pragma unroll
        for (int i = 0; i < 8; ++i)
#pragma unroll
            for (int j = 0; j < 4; ++j) {
                int dd = base + j - i;
                int rr = min(max(dd, -MAXREL), MAXREL) + MAXREL;
                acc[i][j] += qrel[(qg + i) * NREL + rr];
            }

        // ---- Register softmax: max/sum across 16 lanes per row ----
        float fac[8], ls[8], mnew[8];
#pragma unroll
        for (int i = 0; i < 8; ++i) {
            float m = fmaxf(fmaxf(acc[i][0], acc[i][1]), fmaxf(acc[i][2], acc[i][3]));
            RED16MAX(m);
            float mold = rowm[qg + i];
            mnew[i] = fmaxf(mold, m);
            fac[i] = __expf(mold - mnew[i]);
            float s = 0.f;
#pragma unroll
            for (int j = 0; j < 4; ++j) {
                acc[i][j] = __expf(acc[i][j] - mnew[i]);   // acc now = p
                s += acc[i][j];
            }
            RED16SUM(s);
            ls[i] = s;
        }
        __syncwarp();
        if (l16 == 0) {
#pragma unroll
            for (int i = 0; i < 8; ++i) {
                rowm[qg + i] = mnew[i];
                rowl[qg + i] = rowl[qg + i] * fac[i] + ls[i];
            }
        }

        // ---- srel rescale (each (row,bucket) owned by one lane) ----
#pragma unroll
        for (int i = 0; i < 8; ++i) {
            srel[(qg + i) * NREL + l16]      *= fac[i];
            srel[(qg + i) * NREL + 16 + l16] *= fac[i];
            if (l16 == 0) srel[(qg + i) * NREL + 32] *= fac[i];
        }
        __syncwarp();

        // ---- srel accumulate ----
        const int diff = k0 - q0;
        if (diff <= -128) {           // all dd <= -MAXREL -> bucket 0
            if (l16 == 0)
#pragma unroll
                for (int i = 0; i < 8; ++i) srel[(qg + i) * NREL] += ls[i];
        } else if (diff >= 128) {     // all dd >= MAXREL -> bucket 32
            if (l16 == 0)
#pragma unroll
                for (int i = 0; i < 8; ++i) srel[(qg + i) * NREL + 32] += ls[i];
        } else {                      // general: interior buckets unique per k
#pragma unroll
            for (int i = 0; i < 8; ++i) {
                float c0 = 0.f, c32 = 0.f;
#pragma unroll
                for (int j = 0; j < 4; ++j) {
                    int dd = base + j - i;
                    if (dd <= -MAXREL)      c0  += acc[i][j];
                    else if (dd >= MAXREL)  c32 += acc[i][j];
                    else srel[(qg + i) * NREL + dd + MAXREL] += acc[i][j];
                }
                RED16SUM(c0);
                RED16SUM(c32);
                if (l16 == 0) {
                    srel[(qg + i) * NREL]      += c0;
                    srel[(qg + i) * NREL + 32] += c32;
                }
            }
        }

        // ---- Write probabilities stT[k][q] ----
#pragma unroll
        for (int j = 0; j < 4; ++j) {
            *(float4*)&stT[(kg + j) * LDS + qg] =
                make_float4(acc[0][j], acc[1][j], acc[2][j], acc[3][j]);
            *(float4*)&stT[(kg + j) * LDS + qg + 4] =
                make_float4(acc[4][j], acc[5][j], acc[6][j], acc[7][j]);
        }
        __syncthreads();

        // ---- AV: o[8q][4d] = o*fac + sum_k p[k][q]*v[k][d] ----
#pragma unroll
        for (int i = 0; i < 8; ++i) {
            float f = fac[i];
#pragma unroll
            for (int j = 0; j < 4; ++j) o[i][j] *= f;
        }
#pragma unroll 4
        for (int kc = 0; kc < KT; ++kc) {
            float4 p0 = *(const float4*)&stT[kc * LDS + qg];
            float4 p1 = *(const float4*)&stT[kc * LDS + qg + 4];
            float4 vv = *(const float4*)&vt[kc * LDS + di];
            float pr[8] = {p0.x, p0.y, p0.z, p0.w, p1.x, p1.y, p1.z, p1.w};
            float vr[4] = {vv.x, vv.y, vv.z, vv.w};
#pragma unroll
            for (int i = 0; i < 8; ++i)
#pragma unroll
                for (int j = 0; j < 4; ++j) o[i][j] += pr[i] * vr[j];
        }
        __syncthreads();
    }

    // ---- Finalize: add srel @ rel_v, normalize, write ----
#pragma unroll 3
    for (int rr = 0; rr < NREL; ++rr) {
        float4 rv = *(const float4*)&relv[rr * DH + di];
        float vr[4] = {rv.x, rv.y, rv.z, rv.w};
#pragma unroll
        for (int i = 0; i < 8; ++i) {
            float srv = srel[(qg + i) * NREL + rr];
#pragma unroll
            for (int j = 0; j < 4; ++j) o[i][j] += srv * vr[j];
        }
    }
#pragma unroll
    for (int i = 0; i < 8; ++i) {
        float invl = 1.0f / rowl[qg + i];
        float4 v4 = make_float4(o[i][0] * invl, o[i][1] * invl,
                                o[i][2] * invl, o[i][3] * invl);
        *(float4*)&X[((size_t)b * SEQ + q0 + qg + i) * DMODEL + h * DH + di] = v4;
    }
}

// ---------------------------------------------------------------------------
extern "C" void kernel_launch(void* const* d_in, const int* in_sizes, int n_in,
                              void* d_out, int out_size)
{
    const float* query = (const float*)d_in[0];
    const float* key   = (const float*)d_in[1];
    const float* value = (const float*)d_in[2];
    const float* Wq = (const float*)d_in[3];  const float* bq = (const float*)d_in[4];
    const float* Wk = (const float*)d_in[5];  const float* bk = (const float*)d_in[6];
    const float* Wv = (const float*)d_in[7];  const float* bv = (const float*)d_in[8];
    const float* Wo = (const float*)d_in[9];  const float* bo = (const float*)d_in[10];
    const float* relk = (const float*)d_in[11];
    const float* relv = (const float*)d_in[12];
    float* out = (float*)d_out;

    float *gq, *gk, *gv, *gx;
    cudaGetSymbolAddress((void**)&gq, g_q);
    cudaGetSymbolAddress((void**)&gk, g_k);
    cudaGetSymbolAddress((void**)&gv, g_v);
    cudaGetSymbolAddress((void**)&gx, g_x);

    const int attn_smem = ATTN_SMEM_FLOATS * sizeof(float);   // ~85 KB
    cudaFuncSetAttribute(attn_kernel,
                         cudaFuncAttributeMaxDynamicSharedMemorySize, attn_smem);

    // Fused Q/K/V projections: 384 CTAs in one wave set
    dim3 qkvgrid(DMODEL / 128, MROWS / 128, 3);   // (8, 16, 3)
    sgemm_bias_qkv<<<qkvgrid, 256>>>(query, key, value,
                                     Wq, Wk, Wv, bq, bk, bv,
                                     gq, gk, gv, DMODEL, DMODEL);

    dim3 agrid(SEQ / QT, NHEAD, BATCH);           // (16, 16, 2)
    attn_kernel<<<agrid, 128, attn_smem>>>(gq, gk, gv, relk, relv, gx);

    dim3 ggrid(DMODEL / 128, MROWS / 128);        // (8, 16)
    sgemm_bias<<<ggrid, 256>>>(gx, Wo, bo, out, DMODEL, DMODEL);
}